// round 13
// baseline (speedup 1.0000x reference)
#include <cuda_runtime.h>
#include <cuda_bf16.h>
#include <cstdint>

// AtomicComposition: counts[s][k] = #atoms in structure s with species == all_species[k]
// species:            d_in[2]  int32  [n_atoms]
// structure_offsets:  d_in[8]  int32 OR int64 [n_structures] (CSR starts) -- dtype probed on device
// all_species:        d_in[9]  int32  [n_species]
// out: float32 [n_structures, n_species]

__device__ __forceinline__ bool probe_is64(const void* offs, int n_structures,
                                           long long n_atoms) {
    if (n_structures <= 1) return true;
    const long long probe = ((const long long*)offs)[1];
    return (probe >= 0 && probe <= n_atoms);
}

__device__ __forceinline__ int load_offset32(const void* offs, int i, bool is64) {
    if (is64) return (int)((const long long*)offs)[i];
    return ((const int*)offs)[i];
}

// pack low bytes of 4 ints into one word: [x.b0, y.b0, z.b0, w.b0]
__device__ __forceinline__ unsigned pack_bytes(const int4 v) {
    const unsigned t0 = __byte_perm((unsigned)v.x, (unsigned)v.y, 0x0040);
    const unsigned t1 = __byte_perm((unsigned)v.z, (unsigned)v.w, 0x0040);
    return __byte_perm(t0, t1, 0x5410);
}

#define SPW 8   // structures per warp (4 chunks of 2, double-buffered)

// NS=5. Chunked double-buffer pipeline: prefetch chunk c+1 (4 LDG.128) before
// computing chunk c (2 structures, dp4a byte-SIMD). Keeps every warp's loads
// in flight continuously instead of one synchronized burst.
__global__ __launch_bounds__(256, 3) void atomic_composition_pipe2(
    const int* __restrict__ species,
    const void* __restrict__ offsets,
    const int* __restrict__ all_species,
    float* __restrict__ out,
    int n_structures,
    int n_atoms)
{
    const int tid   = threadIdx.x;
    const int gwarp = (blockIdx.x * blockDim.x + tid) >> 5;
    const int lid   = tid & 31;
    const int s0    = gwarp * SPW;
    if (s0 >= n_structures) return;

    const bool is64 = probe_is64(offsets, n_structures, (long long)n_atoms);

    // offsets[s0 .. s0+SPW] loaded lane-parallel, distributed by shfl
    int my_off = n_atoms;
    if (lid <= SPW) {
        const int idx = s0 + lid;
        my_off = (idx < n_structures) ? load_offset32(offsets, idx, is64) : n_atoms;
    }
    const int start0 = __shfl_sync(0xFFFFFFFFu, my_off, 0);

    const int sp0 = __ldg(&all_species[0]);
    const int sp1 = __ldg(&all_species[1]);
    const int sp2 = __ldg(&all_species[2]);
    const int sp3 = __ldg(&all_species[3]);
    const int sp4 = __ldg(&all_species[4]);

    // uniform fast path: SPW contiguous structures of exactly 256 atoms each
    const bool uni = __all_sync(0xFFFFFFFFu,
                                (lid > SPW) || (my_off == start0 + lid * 256));

    if (uni && (s0 + SPW <= n_structures) && ((start0 & 3) == 0)) {
        const int4* __restrict__ B = reinterpret_cast<const int4*>(species + start0);

        const unsigned q0 = (unsigned)sp0 * 0x01010101u;
        const unsigned q1 = (unsigned)sp1 * 0x01010101u;
        const unsigned q2 = (unsigned)sp2 * 0x01010101u;
        const unsigned q3 = (unsigned)sp3 * 0x01010101u;
        const unsigned q4 = (unsigned)sp4 * 0x01010101u;
        const int ONE = 0x01010101;

        // chunk = 2 structures = 4 int4 per lane (indices chunk*128 + i*32 + lid)
        int4 bufA[4], bufB[4];
#pragma unroll
        for (int i = 0; i < 4; ++i) bufA[i] = B[i * 32 + lid];

#pragma unroll
        for (int c = 0; c < 4; ++c) {
            int4* cur = (c & 1) ? bufB : bufA;
            int4* nxt = (c & 1) ? bufA : bufB;
            // prefetch next chunk BEFORE computing this one
            if (c < 3) {
#pragma unroll
                for (int i = 0; i < 4; ++i)
                    nxt[i] = B[(c + 1) * 128 + i * 32 + lid];
            }

            // byte-SIMD valid only if all values fit in a byte (true: z<119)
            int orall = cur[0].x | cur[0].y | cur[0].z | cur[0].w
                      | cur[1].x | cur[1].y | cur[1].z | cur[1].w
                      | cur[2].x | cur[2].y | cur[2].z | cur[2].w
                      | cur[3].x | cur[3].y | cur[3].z | cur[3].w;
            const bool bytesafe =
                __all_sync(0xFFFFFFFFu, (orall & ~0xFF) == 0 && orall >= 0);

#pragma unroll
            for (int j = 0; j < 2; ++j) {           // 2 structures per chunk
                const int4 u = cur[2 * j];
                const int4 v = cur[2 * j + 1];
                int c0, c1, c2, c3, c4;
                if (bytesafe) {
                    const unsigned w0 = pack_bytes(u);
                    const unsigned w1 = pack_bytes(v);
                    c0 = c1 = c2 = c3 = c4 = 0;
                    c0 = __dp4a((int)__vcmpeq4(w0, q0), ONE, c0);
                    c1 = __dp4a((int)__vcmpeq4(w0, q1), ONE, c1);
                    c2 = __dp4a((int)__vcmpeq4(w0, q2), ONE, c2);
                    c3 = __dp4a((int)__vcmpeq4(w0, q3), ONE, c3);
                    c4 = __dp4a((int)__vcmpeq4(w0, q4), ONE, c4);
                    c0 = __dp4a((int)__vcmpeq4(w1, q0), ONE, c0);
                    c1 = __dp4a((int)__vcmpeq4(w1, q1), ONE, c1);
                    c2 = __dp4a((int)__vcmpeq4(w1, q2), ONE, c2);
                    c3 = __dp4a((int)__vcmpeq4(w1, q3), ONE, c3);
                    c4 = __dp4a((int)__vcmpeq4(w1, q4), ONE, c4);
                    c0 = -c0; c1 = -c1; c2 = -c2; c3 = -c3; c4 = -c4;
                } else {
                    c0 = (u.x==sp0)+(u.y==sp0)+(u.z==sp0)+(u.w==sp0)
                       + (v.x==sp0)+(v.y==sp0)+(v.z==sp0)+(v.w==sp0);
                    c1 = (u.x==sp1)+(u.y==sp1)+(u.z==sp1)+(u.w==sp1)
                       + (v.x==sp1)+(v.y==sp1)+(v.z==sp1)+(v.w==sp1);
                    c2 = (u.x==sp2)+(u.y==sp2)+(u.z==sp2)+(u.w==sp2)
                       + (v.x==sp2)+(v.y==sp2)+(v.z==sp2)+(v.w==sp2);
                    c3 = (u.x==sp3)+(u.y==sp3)+(u.z==sp3)+(u.w==sp3)
                       + (v.x==sp3)+(v.y==sp3)+(v.z==sp3)+(v.w==sp3);
                    c4 = (u.x==sp4)+(u.y==sp4)+(u.z==sp4)+(u.w==sp4)
                       + (v.x==sp4)+(v.y==sp4)+(v.z==sp4)+(v.w==sp4);
                }

                // per-lane <= 8, warp sums <= 256 -> 10-bit fields safe
                int pA = c0 | (c1 << 10) | (c2 << 20);
                int pB = c3 | (c4 << 10);
                pA = __reduce_add_sync(0xFFFFFFFFu, pA);
                pB = __reduce_add_sync(0xFFFFFFFFu, pB);

                const int word = (lid < 3) ? pA : pB;
                const int sh   = (lid < 3) ? (10 * lid) : (10 * (lid - 3));
                if (lid < 5)
                    out[(s0 + 2 * c + j) * 5 + lid] = (float)((word >> sh) & 1023);
            }
        }
        return;
    }

    // general fallback: per-structure loop (any sizes/alignment)
    for (int g = 0; g < SPW; ++g) {
        const int s = s0 + g;
        if (s >= n_structures) break;
        const int start = __shfl_sync(0xFFFFFFFFu, my_off, g);
        const int end   = __shfl_sync(0xFFFFFFFFu, my_off, g + 1);

        int c0 = 0, c1 = 0, c2 = 0, c3 = 0, c4 = 0;
        for (int j = start + lid; j < end; j += 32) {
            const int z = species[j];
            c0 += (z == sp0); c1 += (z == sp1); c2 += (z == sp2);
            c3 += (z == sp3); c4 += (z == sp4);
        }
        c0 = __reduce_add_sync(0xFFFFFFFFu, c0);
        c1 = __reduce_add_sync(0xFFFFFFFFu, c1);
        c2 = __reduce_add_sync(0xFFFFFFFFu, c2);
        c3 = __reduce_add_sync(0xFFFFFFFFu, c3);
        c4 = __reduce_add_sync(0xFFFFFFFFu, c4);
        if (lid == 0) {
            float* o = out + s * 5;
            o[0] = (float)c0; o[1] = (float)c1; o[2] = (float)c2;
            o[3] = (float)c3; o[4] = (float)c4;
        }
    }
}

// Fallback for arbitrary n_species (shared-memory counters, CTA per structure)
__global__ __launch_bounds__(64) void atomic_composition_generic(
    const int* __restrict__ species,
    const void* __restrict__ offsets,
    const int* __restrict__ all_species,
    float* __restrict__ out,
    int n_structures,
    long long n_atoms,
    int n_species)
{
    extern __shared__ int shc[];
    const int s   = blockIdx.x;
    const int tid = threadIdx.x;
    for (int k = tid; k < n_species; k += 64) shc[k] = 0;
    __syncthreads();

    const bool is64 = probe_is64(offsets, n_structures, n_atoms);
    const long long start = is64 ? ((const long long*)offsets)[s]
                                 : (long long)((const int*)offsets)[s];
    long long end = n_atoms;
    if (s + 1 < n_structures)
        end = is64 ? ((const long long*)offsets)[s + 1]
                   : (long long)((const int*)offsets)[s + 1];

    for (long long j = start + tid; j < end; j += 64) {
        const int z = species[j];
        for (int k = 0; k < n_species; ++k)
            if (z == __ldg(&all_species[k])) atomicAdd(&shc[k], 1);
    }
    __syncthreads();
    for (int k = tid; k < n_species; k += 64)
        out[(long long)s * n_species + k] = (float)shc[k];
}

extern "C" void kernel_launch(void* const* d_in, const int* in_sizes, int n_in,
                              void* d_out, int out_size)
{
    const int*  species     = (const int*)d_in[2];
    const void* offsets     = d_in[8];
    const int*  all_species = (const int*)d_in[9];
    float*      out         = (float*)d_out;

    const long long n_atoms      = (long long)in_sizes[2];
    const int       n_structures = in_sizes[8];
    const int       n_species    = in_sizes[9];

    if (n_species == 5 && n_atoms < 0x7FFFFFFFLL) {
        const int warps = (n_structures + SPW - 1) / SPW;   // 4096
        const int ctas  = (warps * 32 + 255) / 256;          // 512 CTAs (~3.5/SM)
        atomic_composition_pipe2<<<ctas, 256>>>(
            species, offsets, all_species, out, n_structures, (int)n_atoms);
    } else {
        atomic_composition_generic<<<n_structures, 64, n_species * sizeof(int)>>>(
            species, offsets, all_species, out, n_structures, n_atoms, n_species);
    }
}

// round 14
// speedup vs baseline: 1.3721x; 1.3721x over previous
#include <cuda_runtime.h>
#include <cuda_bf16.h>
#include <cstdint>

// AtomicComposition: counts[s][k] = #atoms in structure s with species == all_species[k]
// species:            d_in[2]  int32  [n_atoms]
// structure_offsets:  d_in[8]  int32 OR int64 [n_structures] (CSR starts) -- dtype probed on device
// all_species:        d_in[9]  int32  [n_species]
// out: float32 [n_structures, n_species]

__device__ __forceinline__ bool probe_is64(const void* offs, int n_structures,
                                           long long n_atoms) {
    if (n_structures <= 1) return true;
    const long long probe = ((const long long*)offs)[1];
    return (probe >= 0 && probe <= n_atoms);
}

__device__ __forceinline__ int load_offset32(const void* offs, int i, bool is64) {
    if (is64) return (int)((const long long*)offs)[i];
    return ((const int*)offs)[i];
}

// pack low bytes of 4 ints into one word: [x.b0, y.b0, z.b0, w.b0]
__device__ __forceinline__ unsigned pack_bytes(const int4 v) {
    const unsigned t0 = __byte_perm((unsigned)v.x, (unsigned)v.y, 0x0040);
    const unsigned t1 = __byte_perm((unsigned)v.z, (unsigned)v.w, 0x0040);
    return __byte_perm(t0, t1, 0x5410);
}

__device__ __forceinline__ uint32_t smem_u32(const void* p) {
    return (uint32_t)__cvta_generic_to_shared(p);
}

#define CP_ASYNC16(dst_u32, src_ptr) \
    asm volatile("cp.async.cg.shared.global [%0], [%1], 16;" \
                 :: "r"(dst_u32), "l"(src_ptr) : "memory")
#define CP_COMMIT() asm volatile("cp.async.commit_group;" ::: "memory")
template <int N>
__device__ __forceinline__ void cp_wait() {
    asm volatile("cp.async.wait_group %0;" :: "n"(N) : "memory");
}

#define SPW 8   // structures per warp; depth-4 cp.async ring

// NS=5. Warp-autonomous cp.async pipeline: global->smem copies bypass the
// register file / L1-fill path; commit-group depth (4 structures = 4KB/warp)
// keeps loads in flight continuously without register pressure.
__global__ __launch_bounds__(256) void atomic_composition_cpa(
    const int* __restrict__ species,
    const void* __restrict__ offsets,
    const int* __restrict__ all_species,
    float* __restrict__ out,
    int n_structures,
    int n_atoms)
{
    __shared__ int4 ring[8][4][64];   // [warp][stage][64 x int4 = 1KB]

    const int tid = threadIdx.x;
    const int wid = tid >> 5;
    const int lid = tid & 31;
    const int gwarp = blockIdx.x * 8 + wid;
    const int s0 = gwarp * SPW;
    if (s0 >= n_structures) return;

    const bool is64 = probe_is64(offsets, n_structures, (long long)n_atoms);

    int my_off = n_atoms;
    if (lid <= SPW) {
        const int idx = s0 + lid;
        my_off = (idx < n_structures) ? load_offset32(offsets, idx, is64) : n_atoms;
    }
    const int start0 = __shfl_sync(0xFFFFFFFFu, my_off, 0);

    const int sp0 = __ldg(&all_species[0]);
    const int sp1 = __ldg(&all_species[1]);
    const int sp2 = __ldg(&all_species[2]);
    const int sp3 = __ldg(&all_species[3]);
    const int sp4 = __ldg(&all_species[4]);

    const bool uni = __all_sync(0xFFFFFFFFu,
                                (lid > SPW) || (my_off == start0 + lid * 256));

    if (uni && (s0 + SPW <= n_structures) && ((start0 & 3) == 0)) {
        const char* __restrict__ gbase = (const char*)(species + start0);
        const uint32_t sbase = smem_u32(&ring[wid][0][0]);

        const unsigned q0 = (unsigned)sp0 * 0x01010101u;
        const unsigned q1 = (unsigned)sp1 * 0x01010101u;
        const unsigned q2 = (unsigned)sp2 * 0x01010101u;
        const unsigned q3 = (unsigned)sp3 * 0x01010101u;
        const unsigned q4 = (unsigned)sp4 * 0x01010101u;
        const int ONE = 0x01010101;

        // issue(g): copy structure g's 1KB into stage g&3; one commit group
        auto issue = [&](int g) {
            const uint32_t dst = sbase + (unsigned)(g & 3) * 1024u + (unsigned)lid * 16u;
            const char* src = gbase + (size_t)g * 1024 + (size_t)lid * 16;
            CP_ASYNC16(dst, src);
            CP_ASYNC16(dst + 512u, src + 512);
            CP_COMMIT();
        };

        auto compute = [&](int g) {
            const int4 u = ring[wid][g & 3][lid];
            const int4 v = ring[wid][g & 3][32 + lid];

            const int orall = u.x | u.y | u.z | u.w | v.x | v.y | v.z | v.w;
            const bool bytesafe =
                __all_sync(0xFFFFFFFFu, (orall & ~0xFF) == 0 && orall >= 0);

            int c0, c1, c2, c3, c4;
            if (bytesafe) {
                const unsigned w0 = pack_bytes(u);
                const unsigned w1 = pack_bytes(v);
                c0 = c1 = c2 = c3 = c4 = 0;
                c0 = __dp4a((int)__vcmpeq4(w0, q0), ONE, c0);
                c1 = __dp4a((int)__vcmpeq4(w0, q1), ONE, c1);
                c2 = __dp4a((int)__vcmpeq4(w0, q2), ONE, c2);
                c3 = __dp4a((int)__vcmpeq4(w0, q3), ONE, c3);
                c4 = __dp4a((int)__vcmpeq4(w0, q4), ONE, c4);
                c0 = __dp4a((int)__vcmpeq4(w1, q0), ONE, c0);
                c1 = __dp4a((int)__vcmpeq4(w1, q1), ONE, c1);
                c2 = __dp4a((int)__vcmpeq4(w1, q2), ONE, c2);
                c3 = __dp4a((int)__vcmpeq4(w1, q3), ONE, c3);
                c4 = __dp4a((int)__vcmpeq4(w1, q4), ONE, c4);
                c0 = -c0; c1 = -c1; c2 = -c2; c3 = -c3; c4 = -c4;
            } else {
                c0 = (u.x==sp0)+(u.y==sp0)+(u.z==sp0)+(u.w==sp0)
                   + (v.x==sp0)+(v.y==sp0)+(v.z==sp0)+(v.w==sp0);
                c1 = (u.x==sp1)+(u.y==sp1)+(u.z==sp1)+(u.w==sp1)
                   + (v.x==sp1)+(v.y==sp1)+(v.z==sp1)+(v.w==sp1);
                c2 = (u.x==sp2)+(u.y==sp2)+(u.z==sp2)+(u.w==sp2)
                   + (v.x==sp2)+(v.y==sp2)+(v.z==sp2)+(v.w==sp2);
                c3 = (u.x==sp3)+(u.y==sp3)+(u.z==sp3)+(u.w==sp3)
                   + (v.x==sp3)+(v.y==sp3)+(v.z==sp3)+(v.w==sp3);
                c4 = (u.x==sp4)+(u.y==sp4)+(u.z==sp4)+(u.w==sp4)
                   + (v.x==sp4)+(v.y==sp4)+(v.z==sp4)+(v.w==sp4);
            }

            int pA = c0 | (c1 << 10) | (c2 << 20);
            int pB = c3 | (c4 << 10);
            pA = __reduce_add_sync(0xFFFFFFFFu, pA);
            pB = __reduce_add_sync(0xFFFFFFFFu, pB);

            const int word = (lid < 3) ? pA : pB;
            const int sh   = (lid < 3) ? (10 * lid) : (10 * (lid - 3));
            if (lid < 5)
                out[(s0 + g) * 5 + lid] = (float)((word >> sh) & 1023);
        };

        // prologue: 4 groups in flight
        issue(0); issue(1); issue(2); issue(3);
        // steady state: wait oldest, compute, refill
        cp_wait<3>(); compute(0); issue(4);
        cp_wait<3>(); compute(1); issue(5);
        cp_wait<3>(); compute(2); issue(6);
        cp_wait<3>(); compute(3); issue(7);
        // drain
        cp_wait<3>(); compute(4);
        cp_wait<2>(); compute(5);
        cp_wait<1>(); compute(6);
        cp_wait<0>(); compute(7);
        return;
    }

    // general fallback: per-structure loop (any sizes/alignment)
    for (int g = 0; g < SPW; ++g) {
        const int s = s0 + g;
        if (s >= n_structures) break;
        const int start = __shfl_sync(0xFFFFFFFFu, my_off, g);
        const int end   = __shfl_sync(0xFFFFFFFFu, my_off, g + 1);

        int c0 = 0, c1 = 0, c2 = 0, c3 = 0, c4 = 0;
        for (int j = start + lid; j < end; j += 32) {
            const int z = species[j];
            c0 += (z == sp0); c1 += (z == sp1); c2 += (z == sp2);
            c3 += (z == sp3); c4 += (z == sp4);
        }
        c0 = __reduce_add_sync(0xFFFFFFFFu, c0);
        c1 = __reduce_add_sync(0xFFFFFFFFu, c1);
        c2 = __reduce_add_sync(0xFFFFFFFFu, c2);
        c3 = __reduce_add_sync(0xFFFFFFFFu, c3);
        c4 = __reduce_add_sync(0xFFFFFFFFu, c4);
        if (lid == 0) {
            float* o = out + s * 5;
            o[0] = (float)c0; o[1] = (float)c1; o[2] = (float)c2;
            o[3] = (float)c3; o[4] = (float)c4;
        }
    }
}

// Fallback for arbitrary n_species (shared-memory counters, CTA per structure)
__global__ __launch_bounds__(64) void atomic_composition_generic(
    const int* __restrict__ species,
    const void* __restrict__ offsets,
    const int* __restrict__ all_species,
    float* __restrict__ out,
    int n_structures,
    long long n_atoms,
    int n_species)
{
    extern __shared__ int shc[];
    const int s   = blockIdx.x;
    const int tid = threadIdx.x;
    for (int k = tid; k < n_species; k += 64) shc[k] = 0;
    __syncthreads();

    const bool is64 = probe_is64(offsets, n_structures, n_atoms);
    const long long start = is64 ? ((const long long*)offsets)[s]
                                 : (long long)((const int*)offsets)[s];
    long long end = n_atoms;
    if (s + 1 < n_structures)
        end = is64 ? ((const long long*)offsets)[s + 1]
                   : (long long)((const int*)offsets)[s + 1];

    for (long long j = start + tid; j < end; j += 64) {
        const int z = species[j];
        for (int k = 0; k < n_species; ++k)
            if (z == __ldg(&all_species[k])) atomicAdd(&shc[k], 1);
    }
    __syncthreads();
    for (int k = tid; k < n_species; k += 64)
        out[(long long)s * n_species + k] = (float)shc[k];
}

extern "C" void kernel_launch(void* const* d_in, const int* in_sizes, int n_in,
                              void* d_out, int out_size)
{
    const int*  species     = (const int*)d_in[2];
    const void* offsets     = d_in[8];
    const int*  all_species = (const int*)d_in[9];
    float*      out         = (float*)d_out;

    const long long n_atoms      = (long long)in_sizes[2];
    const int       n_structures = in_sizes[8];
    const int       n_species    = in_sizes[9];

    if (n_species == 5 && n_atoms < 0x7FFFFFFFLL) {
        const int warps = (n_structures + SPW - 1) / SPW;   // 4096
        const int ctas  = (warps + 7) / 8;                   // 512 CTAs
        atomic_composition_cpa<<<ctas, 256>>>(
            species, offsets, all_species, out, n_structures, (int)n_atoms);
    } else {
        atomic_composition_generic<<<n_structures, 64, n_species * sizeof(int)>>>(
            species, offsets, all_species, out, n_structures, n_atoms, n_species);
    }
}

// round 15
// speedup vs baseline: 1.3761x; 1.0029x over previous
#include <cuda_runtime.h>
#include <cuda_bf16.h>
#include <cstdint>

// AtomicComposition: counts[s][k] = #atoms in structure s with species == all_species[k]
// species:            d_in[2]  int32  [n_atoms]
// structure_offsets:  d_in[8]  int32 OR int64 [n_structures] (CSR starts) -- dtype probed on device
// all_species:        d_in[9]  int32  [n_species]
// out: float32 [n_structures, n_species]

__device__ __forceinline__ bool probe_is64(const void* offs, int n_structures,
                                           long long n_atoms) {
    if (n_structures <= 1) return true;
    const long long probe = ((const long long*)offs)[1];
    return (probe >= 0 && probe <= n_atoms);
}

__device__ __forceinline__ int load_offset32(const void* offs, int i, bool is64) {
    if (is64) return (int)((const long long*)offs)[i];
    return ((const int*)offs)[i];
}

// pack low bytes of 4 ints into one word: [x.b0, y.b0, z.b0, w.b0]
__device__ __forceinline__ unsigned pack_bytes(const int4 v) {
    const unsigned t0 = __byte_perm((unsigned)v.x, (unsigned)v.y, 0x0040);
    const unsigned t1 = __byte_perm((unsigned)v.z, (unsigned)v.w, 0x0040);
    return __byte_perm(t0, t1, 0x5410);
}

__device__ __forceinline__ uint32_t smem_u32(const void* p) {
    return (uint32_t)__cvta_generic_to_shared(p);
}

__device__ __forceinline__ void mbar_init(uint32_t mbar, uint32_t count) {
    asm volatile("mbarrier.init.shared.b64 [%0], %1;" :: "r"(mbar), "r"(count) : "memory");
}
__device__ __forceinline__ void mbar_expect_tx(uint32_t mbar, uint32_t bytes) {
    asm volatile("mbarrier.arrive.expect_tx.shared.b64 _, [%0], %1;"
                 :: "r"(mbar), "r"(bytes) : "memory");
}
__device__ __forceinline__ void mbar_wait(uint32_t mbar, uint32_t parity) {
    uint32_t done;
    asm volatile(
        "{\n\t.reg .pred p;\n\t"
        "mbarrier.try_wait.parity.shared.b64 p, [%1], %2;\n\t"
        "selp.b32 %0, 1, 0, p;\n\t}"
        : "=r"(done) : "r"(mbar), "r"(parity) : "memory");
    while (!done) {
        asm volatile(
            "{\n\t.reg .pred p;\n\t"
            "mbarrier.try_wait.parity.shared.b64 p, [%1], %2, 0x989680;\n\t"
            "selp.b32 %0, 1, 0, p;\n\t}"
            : "=r"(done) : "r"(mbar), "r"(parity) : "memory");
    }
}
__device__ __forceinline__ void tma_bulk_g2s(uint32_t dst, const void* src,
                                             uint32_t bytes, uint32_t mbar) {
    asm volatile(
        "cp.async.bulk.shared::cluster.global.mbarrier::complete_tx::bytes "
        "[%0], [%1], %2, [%3];"
        :: "r"(dst), "l"(src), "r"(bytes), "r"(mbar) : "memory");
}

#define STRUCTS_PER_CTA 32      // 32 x 1KB = 32KB, two 16KB TMA stages
#define STAGE_BYTES     16384

// NS=5. CTA owns 32 contiguous 256-atom structures. Two bulk TMA loads
// (16KB each) bring everything into smem; the TMA engine generates all line
// requests autonomously, bypassing the per-SM LSU/L1tex request path.
// Warp w processes structures {2w, 2w+1} of each stage from smem.
__global__ __launch_bounds__(256) void atomic_composition_tma(
    const int* __restrict__ species,
    const void* __restrict__ offsets,
    const int* __restrict__ all_species,
    float* __restrict__ out,
    int n_structures,
    int n_atoms)
{
    __shared__ alignas(128) int4 stage[2][STAGE_BYTES / 16];
    __shared__ alignas(8) uint64_t mbar_mem[2];
    __shared__ int sh_base;

    const int tid = threadIdx.x;
    const int wid = tid >> 5;
    const int lid = tid & 31;
    const int s0  = blockIdx.x * STRUCTS_PER_CTA;
    if (s0 >= n_structures) return;

    const bool is64 = probe_is64(offsets, n_structures, (long long)n_atoms);

    const uint32_t mb0 = smem_u32(&mbar_mem[0]);
    const uint32_t mb1 = smem_u32(&mbar_mem[1]);

    if (tid == 0) {
        mbar_init(mb0, 1);
        mbar_init(mb1, 1);
        sh_base = load_offset32(offsets, s0, is64);
    }
    __syncthreads();

    const int base = sh_base;

    // uniformity: offsets[s0+t] == base + 256*t for t=0..32 (end via n_atoms)
    int pred = 1;
    if (tid <= STRUCTS_PER_CTA) {
        const int idx = s0 + tid;
        const int o = (idx < n_structures) ? load_offset32(offsets, idx, is64)
                                           : n_atoms;
        pred = (o == base + tid * 256);
    }
    const int nuni = __syncthreads_count(pred);
    const bool fast = (nuni == 256) && (s0 + STRUCTS_PER_CTA <= n_structures)
                      && ((base & 3) == 0);

    const int sp0 = __ldg(&all_species[0]);
    const int sp1 = __ldg(&all_species[1]);
    const int sp2 = __ldg(&all_species[2]);
    const int sp3 = __ldg(&all_species[3]);
    const int sp4 = __ldg(&all_species[4]);

    if (fast) {
        if (tid == 0) {
            const char* src = (const char*)(species + base);
            mbar_expect_tx(mb0, STAGE_BYTES);
            tma_bulk_g2s(smem_u32(&stage[0][0]), src, STAGE_BYTES, mb0);
            mbar_expect_tx(mb1, STAGE_BYTES);
            tma_bulk_g2s(smem_u32(&stage[1][0]), src + STAGE_BYTES, STAGE_BYTES, mb1);
        }

        const unsigned q0 = (unsigned)sp0 * 0x01010101u;
        const unsigned q1 = (unsigned)sp1 * 0x01010101u;
        const unsigned q2 = (unsigned)sp2 * 0x01010101u;
        const unsigned q3 = (unsigned)sp3 * 0x01010101u;
        const unsigned q4 = (unsigned)sp4 * 0x01010101u;
        const int ONE = 0x01010101;

#pragma unroll
        for (int st = 0; st < 2; ++st) {
            mbar_wait(st == 0 ? mb0 : mb1, 0);
            const int4* buf = &stage[st][0];

#pragma unroll
            for (int j = 0; j < 2; ++j) {             // 2 structures per warp
                const int sloc = 2 * wid + j;          // 0..15 within stage
                const int4 u = buf[sloc * 64 + lid];
                const int4 v = buf[sloc * 64 + 32 + lid];

                const int orall = u.x | u.y | u.z | u.w | v.x | v.y | v.z | v.w;
                const bool bytesafe =
                    __all_sync(0xFFFFFFFFu, (orall & ~0xFF) == 0 && orall >= 0);

                int c0, c1, c2, c3, c4;
                if (bytesafe) {
                    const unsigned w0 = pack_bytes(u);
                    const unsigned w1 = pack_bytes(v);
                    c0 = c1 = c2 = c3 = c4 = 0;
                    c0 = __dp4a((int)__vcmpeq4(w0, q0), ONE, c0);
                    c1 = __dp4a((int)__vcmpeq4(w0, q1), ONE, c1);
                    c2 = __dp4a((int)__vcmpeq4(w0, q2), ONE, c2);
                    c3 = __dp4a((int)__vcmpeq4(w0, q3), ONE, c3);
                    c4 = __dp4a((int)__vcmpeq4(w0, q4), ONE, c4);
                    c0 = __dp4a((int)__vcmpeq4(w1, q0), ONE, c0);
                    c1 = __dp4a((int)__vcmpeq4(w1, q1), ONE, c1);
                    c2 = __dp4a((int)__vcmpeq4(w1, q2), ONE, c2);
                    c3 = __dp4a((int)__vcmpeq4(w1, q3), ONE, c3);
                    c4 = __dp4a((int)__vcmpeq4(w1, q4), ONE, c4);
                    c0 = -c0; c1 = -c1; c2 = -c2; c3 = -c3; c4 = -c4;
                } else {
                    c0 = (u.x==sp0)+(u.y==sp0)+(u.z==sp0)+(u.w==sp0)
                       + (v.x==sp0)+(v.y==sp0)+(v.z==sp0)+(v.w==sp0);
                    c1 = (u.x==sp1)+(u.y==sp1)+(u.z==sp1)+(u.w==sp1)
                       + (v.x==sp1)+(v.y==sp1)+(v.z==sp1)+(v.w==sp1);
                    c2 = (u.x==sp2)+(u.y==sp2)+(u.z==sp2)+(u.w==sp2)
                       + (v.x==sp2)+(v.y==sp2)+(v.z==sp2)+(v.w==sp2);
                    c3 = (u.x==sp3)+(u.y==sp3)+(u.z==sp3)+(u.w==sp3)
                       + (v.x==sp3)+(v.y==sp3)+(v.z==sp3)+(v.w==sp3);
                    c4 = (u.x==sp4)+(u.y==sp4)+(u.z==sp4)+(u.w==sp4)
                       + (v.x==sp4)+(v.y==sp4)+(v.z==sp4)+(v.w==sp4);
                }

                int pA = c0 | (c1 << 10) | (c2 << 20);
                int pB = c3 | (c4 << 10);
                pA = __reduce_add_sync(0xFFFFFFFFu, pA);
                pB = __reduce_add_sync(0xFFFFFFFFu, pB);

                const int word = (lid < 3) ? pA : pB;
                const int sh   = (lid < 3) ? (10 * lid) : (10 * (lid - 3));
                if (lid < 5)
                    out[(s0 + st * 16 + sloc) * 5 + lid] =
                        (float)((word >> sh) & 1023);
            }
        }
        return;
    }

    // general fallback: 8 warps cover up to 32 structures, direct global reads
    const int s_end = min(s0 + STRUCTS_PER_CTA, n_structures);
    for (int s = s0 + wid; s < s_end; s += 8) {
        const int start = load_offset32(offsets, s, is64);
        const int end   = (s + 1 < n_structures)
                            ? load_offset32(offsets, s + 1, is64) : n_atoms;
        int c0 = 0, c1 = 0, c2 = 0, c3 = 0, c4 = 0;
        for (int j = start + lid; j < end; j += 32) {
            const int z = species[j];
            c0 += (z == sp0); c1 += (z == sp1); c2 += (z == sp2);
            c3 += (z == sp3); c4 += (z == sp4);
        }
        c0 = __reduce_add_sync(0xFFFFFFFFu, c0);
        c1 = __reduce_add_sync(0xFFFFFFFFu, c1);
        c2 = __reduce_add_sync(0xFFFFFFFFu, c2);
        c3 = __reduce_add_sync(0xFFFFFFFFu, c3);
        c4 = __reduce_add_sync(0xFFFFFFFFu, c4);
        if (lid == 0) {
            float* o = out + s * 5;
            o[0] = (float)c0; o[1] = (float)c1; o[2] = (float)c2;
            o[3] = (float)c3; o[4] = (float)c4;
        }
    }
}

// Fallback for arbitrary n_species (shared-memory counters, CTA per structure)
__global__ __launch_bounds__(64) void atomic_composition_generic(
    const int* __restrict__ species,
    const void* __restrict__ offsets,
    const int* __restrict__ all_species,
    float* __restrict__ out,
    int n_structures,
    long long n_atoms,
    int n_species)
{
    extern __shared__ int shc[];
    const int s   = blockIdx.x;
    const int tid = threadIdx.x;
    for (int k = tid; k < n_species; k += 64) shc[k] = 0;
    __syncthreads();

    const bool is64 = probe_is64(offsets, n_structures, n_atoms);
    const long long start = is64 ? ((const long long*)offsets)[s]
                                 : (long long)((const int*)offsets)[s];
    long long end = n_atoms;
    if (s + 1 < n_structures)
        end = is64 ? ((const long long*)offsets)[s + 1]
                   : (long long)((const int*)offsets)[s + 1];

    for (long long j = start + tid; j < end; j += 64) {
        const int z = species[j];
        for (int k = 0; k < n_species; ++k)
            if (z == __ldg(&all_species[k])) atomicAdd(&shc[k], 1);
    }
    __syncthreads();
    for (int k = tid; k < n_species; k += 64)
        out[(long long)s * n_species + k] = (float)shc[k];
}

extern "C" void kernel_launch(void* const* d_in, const int* in_sizes, int n_in,
                              void* d_out, int out_size)
{
    const int*  species     = (const int*)d_in[2];
    const void* offsets     = d_in[8];
    const int*  all_species = (const int*)d_in[9];
    float*      out         = (float*)d_out;

    const long long n_atoms      = (long long)in_sizes[2];
    const int       n_structures = in_sizes[8];
    const int       n_species    = in_sizes[9];

    if (n_species == 5 && n_atoms < 0x7FFFFFFFLL) {
        const int ctas = (n_structures + STRUCTS_PER_CTA - 1) / STRUCTS_PER_CTA; // 1024
        atomic_composition_tma<<<ctas, 256>>>(
            species, offsets, all_species, out, n_structures, (int)n_atoms);
    } else {
        atomic_composition_generic<<<n_structures, 64, n_species * sizeof(int)>>>(
            species, offsets, all_species, out, n_structures, n_atoms, n_species);
    }
}